// round 13
// baseline (speedup 1.0000x reference)
#include <cuda_runtime.h>
#include <cuda_bf16.h>
#include <math.h>

constexpr float kConfidence = 0.9f;
constexpr float kSmoothing  = 0.1f;
constexpr int   WARPS_PER_BLOCK = 8;   // one warp per row

// Preprocessed weights in bf16: g_pad[t*C + c] = 0.1*conf[t][src(c)]/sum(conf[t]),
// 0 at c==t. Row stride C=1000 bf16 = 2000 B.
__device__ __nv_bfloat16 g_pad[1024 * 1024];

// One block per class t. Block 0 also zeroes the output accumulator.
// Signals PDL completion after publishing its g_pad row.
__global__ void __launch_bounds__(256)
prep_conf_kernel(const float* __restrict__ confusion, float* __restrict__ out, int C)
{
    const int t   = blockIdx.x;
    const int tid = threadIdx.x;
    if (t == 0 && tid == 0) out[0] = 0.0f;

    const float* row = confusion + (size_t)t * (C - 1);

    float acc = 0.f;
    for (int j = tid; j < C - 1; j += 256) acc += __ldg(row + j);

    const unsigned FULL = 0xffffffffu;
#pragma unroll
    for (int off = 16; off; off >>= 1) acc += __shfl_down_sync(FULL, acc, off);

    __shared__ float sw[8];
    __shared__ float s_invA;
    if ((tid & 31) == 0) sw[tid >> 5] = acc;
    __syncthreads();
    if (tid == 0) {
        float tot = sw[0] + sw[1] + sw[2] + sw[3] + sw[4] + sw[5] + sw[6] + sw[7];
        s_invA = kSmoothing / tot;
    }
    __syncthreads();
    const float invA = s_invA;

    __nv_bfloat162* dst2 = reinterpret_cast<__nv_bfloat162*>(g_pad + (size_t)t * C);
    const int npairs = C >> 1;   // 500
    for (int i = tid; i < npairs; i += 256) {
        const int c0 = 2 * i, c1 = 2 * i + 1;
        const float v0 = (c0 == t) ? 0.f : __ldg(row + (c0 - (c0 > t))) * invA;
        const float v1 = (c1 == t) ? 0.f : __ldg(row + (c1 - (c1 > t))) * invA;
        dst2[i] = __floats2bfloat162_rn(v0, v1);
    }

    // Publish this block's writes, then allow the dependent grid to proceed.
    __threadfence();
#if __CUDA_ARCH__ >= 900
    cudaTriggerProgrammaticLaunchCompletion();
#endif
}

// Consume one group of 4 classes: pred float4 + weights bf16x4 (as uint2).
__device__ __forceinline__ void consume4(const float4 p, const uint2 c,
                                         float& s0, float& s1, float& d0, float& d1)
{
    s0 += __expf(p.x) + __expf(p.y);
    s1 += __expf(p.z) + __expf(p.w);
    const __nv_bfloat162 c01 = *reinterpret_cast<const __nv_bfloat162*>(&c.x);
    const __nv_bfloat162 c23 = *reinterpret_cast<const __nv_bfloat162*>(&c.y);
    const float2 f01 = __bfloat1622float2(c01);
    const float2 f23 = __bfloat1622float2(c23);
    d0 = fmaf(f01.x, p.x, fmaf(f01.y, p.y, d0));
    d1 = fmaf(f23.x, p.z, fmaf(f23.y, p.w, d1));
}

template <int CN>
__global__ void __launch_bounds__(256, 4)   // 64-reg budget (proven sweet spot)
row_loss_kernel(const float* __restrict__ pred,
                const int*   __restrict__ tgt_raw,
                float* __restrict__ out,
                int Bn, float invB)
{
    constexpr int NVEC = CN / 4;                  // 250
    constexpr int FULL_ITERS = NVEC / 32;         // 7
    constexpr int TAIL = NVEC - FULL_ITERS * 32;  // 26
    constexpr int NITER = FULL_ITERS + 1;         // 8 (incl. predicated tail)

    const int tid  = threadIdx.x;
    const int wid  = tid >> 5;
    const int lane = tid & 31;
    const int row  = blockIdx.x * WARPS_PER_BLOCK + wid;

    // int64 vs int32 target detection (odd 32-bit words all zero => int64).
    const bool is64 = ((tgt_raw[1] | tgt_raw[3] | tgt_raw[5] | tgt_raw[7]) == 0);

    float row_loss = 0.0f;

    if (row < Bn) {
        const int t = is64 ? tgt_raw[2 * row] : tgt_raw[row];

        const float4* prow = reinterpret_cast<const float4*>(pred + (size_t)row * CN);
        const uint2*  crow = reinterpret_cast<const uint2*>(g_pad + (size_t)t * CN);

        // Early target-pred load: issued before the PDL gate, overlaps prep.
        float pt = 0.0f;
        if (lane == 0) pt = __ldcs(pred + (size_t)row * CN + t);

        // PDL gate: wait until the prep grid has published g_pad. pred loads
        // above are already in flight; only weight reads need this ordering.
#if __CUDA_ARCH__ >= 900
        cudaGridDependencySynchronize();
#endif

        float s0 = 0.f, s1 = 0.f, d0 = 0.f, d1 = 0.f;

        // Depth-3 software pipeline; pred streamed (.cs, read once), weights
        // cached (.nc, reused ~33x per class chip-wide).
        float4 p[3];
        uint2  c[3];
#pragma unroll
        for (int k = 0; k < 2; k++) {
            p[k] = __ldcs(prow + lane + k * 32);
            c[k] = __ldg(crow + lane + k * 32);
        }
#pragma unroll
        for (int k = 2; k < NITER; k++) {
            const int slot = k % 3;
            if (k < FULL_ITERS || lane < TAIL) {
                p[slot] = __ldcs(prow + lane + k * 32);
                c[slot] = __ldg(crow + lane + k * 32);
            } else {
                p[slot] = make_float4(-1e30f, -1e30f, -1e30f, -1e30f);  // exp->0
                c[slot] = make_uint2(0u, 0u);
            }
            consume4(p[(k - 2) % 3], c[(k - 2) % 3], s0, s1, d0, d1);
        }
        consume4(p[(NITER - 2) % 3], c[(NITER - 2) % 3], s0, s1, d0, d1);
        consume4(p[(NITER - 1) % 3], c[(NITER - 1) % 3], s0, s1, d0, d1);

        float s   = s0 + s1;
        float dot = d0 + d1;

        const unsigned FULL = 0xffffffffu;
#pragma unroll
        for (int off = 16; off; off >>= 1) {
            s   += __shfl_down_sync(FULL, s,   off);
            dot += __shfl_down_sync(FULL, dot, off);
        }

        if (lane == 0)
            row_loss = __logf(s) - kConfidence * pt - dot;   // dot pre-scaled by 0.1/A
    } else {
#if __CUDA_ARCH__ >= 900
        cudaGridDependencySynchronize();
#endif
    }

    __shared__ float sh[WARPS_PER_BLOCK];
    if (lane == 0) sh[wid] = row_loss;
    __syncthreads();

    if (tid == 0) {
        float acc = sh[0];
#pragma unroll
        for (int w = 1; w < WARPS_PER_BLOCK; w++) acc += sh[w];
        atomicAdd(out, acc * invB);
    }
}

// Generic fallback for unexpected C (runtime trip count).
__global__ void __launch_bounds__(256, 4)
row_loss_kernel_generic(const float* __restrict__ pred,
                        const int*   __restrict__ tgt_raw,
                        float* __restrict__ out,
                        int Bn, int Cn, float invB)
{
    const int tid  = threadIdx.x;
    const int wid  = tid >> 5;
    const int lane = tid & 31;
    const int row  = blockIdx.x * WARPS_PER_BLOCK + wid;
    const bool is64 = ((tgt_raw[1] | tgt_raw[3] | tgt_raw[5] | tgt_raw[7]) == 0);

    float row_loss = 0.0f;
    if (row < Bn) {
        const int t = is64 ? tgt_raw[2 * row] : tgt_raw[row];
        const float4* prow = reinterpret_cast<const float4*>(pred + (size_t)row * Cn);
        const uint2*  crow = reinterpret_cast<const uint2*>(g_pad + (size_t)t * Cn);
        const int nvec = Cn >> 2;
        float s0 = 0.f, s1 = 0.f, d0 = 0.f, d1 = 0.f;
#pragma unroll 4
        for (int j = lane; j < nvec; j += 32) {
            const float4 p4 = __ldg(prow + j);
            const uint2  c4 = __ldg(crow + j);
            consume4(p4, c4, s0, s1, d0, d1);
        }
        float s = s0 + s1, dot = d0 + d1;
        const unsigned FULL = 0xffffffffu;
#pragma unroll
        for (int off = 16; off; off >>= 1) {
            s   += __shfl_down_sync(FULL, s,   off);
            dot += __shfl_down_sync(FULL, dot, off);
        }
        if (lane == 0) {
            const float pt = __ldg(pred + (size_t)row * Cn + t);
            row_loss = __logf(s) - kConfidence * pt - dot;
        }
    }
    __shared__ float sh[WARPS_PER_BLOCK];
    if (lane == 0) sh[wid] = row_loss;
    __syncthreads();
    if (tid == 0) {
        float acc = sh[0];
#pragma unroll
        for (int w = 1; w < WARPS_PER_BLOCK; w++) acc += sh[w];
        atomicAdd(out, acc * invB);
    }
}

extern "C" void kernel_launch(void* const* d_in, const int* in_sizes, int n_in,
                              void* d_out, int out_size) {
    const float* pred      = (const float*)d_in[0];
    const int*   tgt_raw   = (const int*)d_in[1];
    const float* confusion = (const float*)d_in[2];

    const int Bn = in_sizes[1];          // 32768 rows
    const int Cn = in_sizes[0] / Bn;     // 1000 classes

    float* out = (float*)d_out;
    prep_conf_kernel<<<Cn, 256>>>(confusion, out, Cn);

    const float invB = 1.0f / (float)Bn;
    const int grid = (Bn + WARPS_PER_BLOCK - 1) / WARPS_PER_BLOCK;   // 4096

    if (Cn == 1000) {
        // PDL launch: row kernel overlaps prep's tail; its weight reads are
        // gated in-kernel by cudaGridDependencySynchronize().
        cudaLaunchConfig_t cfg = {};
        cfg.gridDim  = dim3(grid);
        cfg.blockDim = dim3(256);
        cfg.dynamicSmemBytes = 0;
        cfg.stream = 0;
        cudaLaunchAttribute attrs[1];
        attrs[0].id = cudaLaunchAttributeProgrammaticStreamSerialization;
        attrs[0].val.programmaticStreamSerializationAllowed = 1;
        cfg.attrs = attrs;
        cfg.numAttrs = 1;

        cudaError_t e = cudaLaunchKernelEx(&cfg, row_loss_kernel<1000>,
                                           pred, tgt_raw, out, Bn, invB);
        if (e != cudaSuccess) {
            (void)cudaGetLastError();   // clear, fall back to plain launch
            row_loss_kernel<1000><<<grid, 256>>>(pred, tgt_raw, out, Bn, invB);
        }
    } else {
        row_loss_kernel_generic<<<grid, 256>>>(pred, tgt_raw, out, Bn, Cn, invB);
    }
}